// round 9
// baseline (speedup 1.0000x reference)
#include <cuda_runtime.h>
#include <cuda_bf16.h>
#include <cstdint>
#include <cstddef>

#define NN 16384
#define MM 16384
#define DD 512

namespace sd {
constexpr int BM = 128;          // rows of x per block (resident in smem, full K)
constexpr int BN = 128;          // cols (y rows) per M-tile
constexpr int KC = 128;          // K chunk for streamed y tiles
constexpr int THREADS = 256;     // 8 warps: 4 (M) x 2 (N)
constexpr int XSTR = 520;        // bf16 stride for resident x tile (conflict-free ldmatrix)
constexpr int YSTR = 136;        // bf16 stride for y stage rows (conflict-free ldmatrix)
constexpr int NCH = DD / KC;     // 4 K-chunks per M-tile
constexpr int XS_BYTES = BM * XSTR * 2;          // 133120
constexpr int YS_STAGE_BYTES = BN * YSTR * 2;    // 34816
constexpr int YS_BYTES = 2 * YS_STAGE_BYTES;     // 69632
constexpr int QS_OFF = XS_BYTES + YS_BYTES;
constexpr int RED_OFF = QS_OFF + BN * 4;
constexpr int SMEM_TOTAL = RED_OFF + BM * 4;     // ~203.8 KB dynamic smem
}

// Scratch (device globals: no allocation allowed)
__device__ __nv_bfloat16 g_xb[(size_t)NN * DD];  // bf16 x
__device__ __nv_bfloat16 g_yb[(size_t)MM * DD];  // bf16 y
__device__ float g_x2[NN];                       // ||x_i||^2
__device__ float g_q[MM];                        // ||y_j||^2 - psi_j

__device__ __forceinline__ void cp16(uint32_t s, const void* g) {
    asm volatile("cp.async.cg.shared.global [%0], [%1], 16;\n" :: "r"(s), "l"(g));
}

#define MMA_BF16(C, A, B0, B1)                                               \
    asm volatile("mma.sync.aligned.m16n8k16.row.col.f32.bf16.bf16.f32 "      \
                 "{%0,%1,%2,%3},{%4,%5,%6,%7},{%8,%9},{%0,%1,%2,%3};"        \
                 : "+f"((C)[0]), "+f"((C)[1]), "+f"((C)[2]), "+f"((C)[3])    \
                 : "r"((A)[0]), "r"((A)[1]), "r"((A)[2]), "r"((A)[3]),       \
                   "r"(B0), "r"(B1))

// ---------------------------------------------------------------------------
// Prep: convert to bf16 + row sum-of-squares (x2, q = y2 - psi)
// ---------------------------------------------------------------------------
__global__ void prep_x_kernel(const float* __restrict__ src) {
    int row = blockIdx.x;
    int t = threadIdx.x;  // 128 threads, D=512 -> one float4 each
    float4 v = reinterpret_cast<const float4*>(src + (size_t)row * DD)[t];
    __nv_bfloat162 p0 = __floats2bfloat162_rn(v.x, v.y);
    __nv_bfloat162 p1 = __floats2bfloat162_rn(v.z, v.w);
    uint2 pk;
    pk.x = *reinterpret_cast<uint32_t*>(&p0);
    pk.y = *reinterpret_cast<uint32_t*>(&p1);
    reinterpret_cast<uint2*>(g_xb + (size_t)row * DD)[t] = pk;
    float s = v.x * v.x + v.y * v.y + v.z * v.z + v.w * v.w;
#pragma unroll
    for (int o = 16; o; o >>= 1) s += __shfl_xor_sync(0xffffffffu, s, o);
    __shared__ float ws[4];
    if ((t & 31) == 0) ws[t >> 5] = s;
    __syncthreads();
    if (t == 0) g_x2[row] = ws[0] + ws[1] + ws[2] + ws[3];
}

__global__ void prep_y_kernel(const float* __restrict__ src, const float* __restrict__ psi) {
    int row = blockIdx.x;
    int t = threadIdx.x;
    float4 v = reinterpret_cast<const float4*>(src + (size_t)row * DD)[t];
    __nv_bfloat162 p0 = __floats2bfloat162_rn(v.x, v.y);
    __nv_bfloat162 p1 = __floats2bfloat162_rn(v.z, v.w);
    uint2 pk;
    pk.x = *reinterpret_cast<uint32_t*>(&p0);
    pk.y = *reinterpret_cast<uint32_t*>(&p1);
    reinterpret_cast<uint2*>(g_yb + (size_t)row * DD)[t] = pk;
    float s = v.x * v.x + v.y * v.y + v.z * v.z + v.w * v.w;
#pragma unroll
    for (int o = 16; o; o >>= 1) s += __shfl_xor_sync(0xffffffffu, s, o);
    __shared__ float ws[4];
    if ((t & 31) == 0) ws[t >> 5] = s;
    __syncthreads();
    if (t == 0) g_q[row] = ws[0] + ws[1] + ws[2] + ws[3] - psi[row];
}

// Seeds out[0] = mean(psi). Runs each replay (re-initializes the accumulator).
__global__ void psi_mean_kernel(const float* __restrict__ psi, float* __restrict__ out) {
    float s = 0.f;
    for (int i = threadIdx.x; i < MM; i += 256) s += psi[i];
#pragma unroll
    for (int o = 16; o; o >>= 1) s += __shfl_xor_sync(0xffffffffu, s, o);
    __shared__ float ws[8];
    if ((threadIdx.x & 31) == 0) ws[threadIdx.x >> 5] = s;
    __syncthreads();
    if (threadIdx.x == 0) {
        float t = 0.f;
#pragma unroll
        for (int i = 0; i < 8; ++i) t += ws[i];
        out[0] = t * (1.0f / (float)MM);
    }
}

// ---------------------------------------------------------------------------
// Main: fused GEMM + row-min. x tile resident in smem (full K), y streamed
// with 2-stage cp.async pipeline. Epilogue per M-tile: rowmin = min(q - 2*dot).
// ---------------------------------------------------------------------------
__device__ __forceinline__ void issue_ys(int mt, int ch, int stage, uint32_t s_ys, int tid) {
    const __nv_bfloat16* gy = g_yb + (size_t)(mt * sd::BN) * DD + ch * sd::KC;
    uint32_t sb = s_ys + (uint32_t)stage * sd::YS_STAGE_BYTES;
#pragma unroll
    for (int i = 0; i < (sd::BN * (sd::KC / 8)) / sd::THREADS; ++i) {  // 8 iters
        int id = tid + i * sd::THREADS;
        int r = id >> 4;     // 16 x 16B segments per row
        int seg = id & 15;
        cp16(sb + (uint32_t)(r * sd::YSTR + seg * 8) * 2, gy + (size_t)r * DD + seg * 8);
    }
    asm volatile("cp.async.commit_group;\n" ::);
}

__global__ __launch_bounds__(sd::THREADS, 1) void semidual_main_kernel(float* __restrict__ out) {
    extern __shared__ char smem[];
    __nv_bfloat16* xs = reinterpret_cast<__nv_bfloat16*>(smem);
    float* qs = reinterpret_cast<float*>(smem + sd::QS_OFF);
    float* red = reinterpret_cast<float*>(smem + sd::RED_OFF);

    const int tid = threadIdx.x;
    const int lane = tid & 31;
    const int warp = tid >> 5;
    const int warpM = warp & 3;   // 4 warps along M (32 rows each)
    const int warpN = warp >> 2;  // 2 warps along N (64 cols each)
    const int row0 = blockIdx.x * sd::BM;

    uint32_t s_xs = (uint32_t)__cvta_generic_to_shared(smem);
    uint32_t s_ys = s_xs + sd::XS_BYTES;

    // Load resident x tile [128][512] bf16 (stride 520 for conflict-free ldmatrix)
#pragma unroll 4
    for (int i = tid; i < sd::BM * (DD / 8); i += sd::THREADS) {
        int r = i >> 6;   // 64 uint4 per row
        int c8 = i & 63;
        uint4 v = *reinterpret_cast<const uint4*>(g_xb + (size_t)(row0 + r) * DD + c8 * 8);
        *reinterpret_cast<uint4*>(xs + r * sd::XSTR + c8 * 8) = v;
    }

    const float INF = __int_as_float(0x7f800000);
    float rowmin[4] = {INF, INF, INF, INF};

    // ldmatrix lane-address components (all non-trans m8n8 x4)
    const int a_r = (lane & 7) + ((lane >> 3) & 1) * 8;  // row within 16 (A, x4)
    const int a_c = (lane >> 4) * 8;                     // k offset (A, x4)
    const int b_n = (lane & 7) + (lane >> 4) * 8;        // n within 16 (B, x4)
    const int b_k = ((lane >> 3) & 1) * 8;               // k offset (B, x4)

    for (int mt = 0; mt < MM / sd::BN; ++mt) {
        if (tid < sd::BN) qs[tid] = g_q[mt * sd::BN + tid];
        issue_ys(mt, 0, 0, s_ys, tid);

        float acc[2][8][4];
#pragma unroll
        for (int a = 0; a < 2; ++a)
#pragma unroll
            for (int b = 0; b < 8; ++b)
#pragma unroll
                for (int c = 0; c < 4; ++c) acc[a][b][c] = 0.f;

#pragma unroll 1
        for (int ch = 0; ch < sd::NCH; ++ch) {
            if (ch + 1 < sd::NCH) {
                issue_ys(mt, ch + 1, (ch + 1) & 1, s_ys, tid);
                asm volatile("cp.async.wait_group 1;\n" ::);
            } else {
                asm volatile("cp.async.wait_group 0;\n" ::);
            }
            __syncthreads();
            uint32_t sb = s_ys + (uint32_t)(ch & 1) * sd::YS_STAGE_BYTES;
#pragma unroll
            for (int ks = 0; ks < sd::KC / 16; ++ks) {
                uint32_t a0[4], a1[4];
                {
                    int kA = ch * sd::KC + ks * 16 + a_c;
                    uint32_t ad0 = s_xs + (uint32_t)((warpM * 32 + 0 + a_r) * sd::XSTR + kA) * 2;
                    uint32_t ad1 = s_xs + (uint32_t)((warpM * 32 + 16 + a_r) * sd::XSTR + kA) * 2;
                    asm volatile("ldmatrix.sync.aligned.m8n8.x4.shared.b16 {%0,%1,%2,%3},[%4];"
                                 : "=r"(a0[0]), "=r"(a0[1]), "=r"(a0[2]), "=r"(a0[3]) : "r"(ad0));
                    asm volatile("ldmatrix.sync.aligned.m8n8.x4.shared.b16 {%0,%1,%2,%3},[%4];"
                                 : "=r"(a1[0]), "=r"(a1[1]), "=r"(a1[2]), "=r"(a1[3]) : "r"(ad1));
                }
#pragma unroll
                for (int tp = 0; tp < 4; ++tp) {
                    uint32_t b0, b1, b2, b3;
                    uint32_t bd = sb + (uint32_t)((warpN * 64 + tp * 16 + b_n) * sd::YSTR +
                                                  ks * 16 + b_k) * 2;
                    // y_s is [n][k] row-major == B col-major (K x N): NON-trans ldmatrix
                    // yields exactly the b-fragment (two k-consecutive elems at fixed n).
                    asm volatile("ldmatrix.sync.aligned.m8n8.x4.shared.b16 {%0,%1,%2,%3},[%4];"
                                 : "=r"(b0), "=r"(b1), "=r"(b2), "=r"(b3) : "r"(bd));
                    MMA_BF16(acc[0][2 * tp],     a0, b0, b1);
                    MMA_BF16(acc[1][2 * tp],     a1, b0, b1);
                    MMA_BF16(acc[0][2 * tp + 1], a0, b2, b3);
                    MMA_BF16(acc[1][2 * tp + 1], a1, b2, b3);
                }
            }
            __syncthreads();
        }

        // Epilogue: rowmin = min(rowmin, q[n] - 2*dot)
        {
            int nq = warpN * 64 + 2 * (lane & 3);
#pragma unroll
            for (int tn = 0; tn < 8; ++tn) {
                float q0 = qs[nq + tn * 8];
                float q1 = qs[nq + tn * 8 + 1];
#pragma unroll
                for (int tm = 0; tm < 2; ++tm) {
                    rowmin[tm * 2 + 0] = fminf(rowmin[tm * 2 + 0],
                        fminf(fmaf(-2.f, acc[tm][tn][0], q0), fmaf(-2.f, acc[tm][tn][1], q1)));
                    rowmin[tm * 2 + 1] = fminf(rowmin[tm * 2 + 1],
                        fminf(fmaf(-2.f, acc[tm][tn][2], q0), fmaf(-2.f, acc[tm][tn][3], q1)));
                }
            }
        }
        __syncthreads();  // protect qs before next tile rewrites it
    }

    // Reduce row mins: quad shuffle -> smem combine across the 2 N-warps
#pragma unroll
    for (int i = 0; i < 4; ++i) {
        float v = rowmin[i];
        v = fminf(v, __shfl_xor_sync(0xffffffffu, v, 1));
        v = fminf(v, __shfl_xor_sync(0xffffffffu, v, 2));
        rowmin[i] = v;
    }
    const int g = lane >> 2;
    if (warpN == 0 && (lane & 3) == 0) {
#pragma unroll
        for (int i = 0; i < 4; ++i)
            red[warpM * 32 + (i >> 1) * 16 + (i & 1) * 8 + g] = rowmin[i];
    }
    __syncthreads();
    if (warpN == 1 && (lane & 3) == 0) {
#pragma unroll
        for (int i = 0; i < 4; ++i) {
            int r = warpM * 32 + (i >> 1) * 16 + (i & 1) * 8 + g;
            red[r] = fminf(red[r], rowmin[i]);
        }
    }
    __syncthreads();

    // Block sum of (x2[r] + rowmin[r]) -> atomic into out
    float s = 0.f;
    if (tid < sd::BM) s = g_x2[row0 + tid] + red[tid];
#pragma unroll
    for (int o = 16; o; o >>= 1) s += __shfl_xor_sync(0xffffffffu, s, o);
    if ((tid & 31) == 0) qs[warp] = s;  // reuse qs as scratch
    __syncthreads();
    if (tid == 0) {
        float tot = 0.f;
#pragma unroll
        for (int i = 0; i < 8; ++i) tot += qs[i];
        atomicAdd(out, tot * (1.0f / (float)NN));
    }
}

// ---------------------------------------------------------------------------
extern "C" void kernel_launch(void* const* d_in, const int* in_sizes, int n_in,
                              void* d_out, int out_size) {
    (void)in_sizes; (void)n_in; (void)out_size;
    const float* x = (const float*)d_in[0];
    const float* y = (const float*)d_in[1];
    const float* psi = (const float*)d_in[2];
    float* out = (float*)d_out;

    prep_x_kernel<<<NN, 128>>>(x);
    prep_y_kernel<<<MM, 128>>>(y, psi);
    psi_mean_kernel<<<1, 256>>>(psi, out);  // seeds out[0] = mean(psi) every replay

    cudaFuncSetAttribute(semidual_main_kernel,
                         cudaFuncAttributeMaxDynamicSharedMemorySize, sd::SMEM_TOTAL);
    semidual_main_kernel<<<NN / sd::BM, sd::THREADS, sd::SMEM_TOTAL>>>(out);
}